// round 3
// baseline (speedup 1.0000x reference)
#include <cuda_runtime.h>
#include <cuda_bf16.h>
#include <cstdint>

#define TOTAL 24576
#define NSEG  64

// ------------------------- device scratch (static) -------------------------
__device__ __nv_bfloat16 g_kv  [TOTAL * 256];   // head-major k|v
__device__ __nv_bfloat16 g_q   [TOTAL * 128];   // head-major q
__device__ float         g_y1a [TOTAL * 256];   // dst_h @ W1a.T + b1'
__device__ __nv_bfloat16 g_msg [TOTAL * 128];   // head-major attention out
__device__ __nv_bfloat16 g_Wkv [256 * 256];     // [Wk;Wv] rows head-major-permuted
__device__ __nv_bfloat16 g_Wqy [384 * 256];     // [Wq(perm); W1a]
__device__ __nv_bfloat16 g_W1bp[256 * 128];     // (W1b@Wm), cols head-major
__device__ __nv_bfloat16 g_W2b [256 * 256];
__device__ float g_bkv[256], g_bqy[384];
__device__ float g_s1[256], g_t1[256], g_s2[256], g_t2[256];
__device__ int g_soff[NSEG + 1], g_doff[NSEG + 1], g_scnt[NSEG], g_dcnt[NSEG];

__device__ __forceinline__ int permc(int n) { return (n & 31) * 4 + (n >> 5); }

// ------------------------------ PTX helpers --------------------------------
__device__ __forceinline__ void ldsm4(uint32_t& r0, uint32_t& r1, uint32_t& r2,
                                      uint32_t& r3, uint32_t a) {
    asm volatile("ldmatrix.sync.aligned.m8n8.x4.shared.b16 {%0,%1,%2,%3}, [%4];"
                 : "=r"(r0), "=r"(r1), "=r"(r2), "=r"(r3) : "r"(a));
}
__device__ __forceinline__ void ldsm4t(uint32_t& r0, uint32_t& r1, uint32_t& r2,
                                       uint32_t& r3, uint32_t a) {
    asm volatile("ldmatrix.sync.aligned.m8n8.x4.trans.shared.b16 {%0,%1,%2,%3}, [%4];"
                 : "=r"(r0), "=r"(r1), "=r"(r2), "=r"(r3) : "r"(a));
}
__device__ __forceinline__ void mma_bf16(float c[4], const uint32_t a[4],
                                         const uint32_t b[2]) {
    asm volatile(
        "mma.sync.aligned.m16n8k16.row.col.f32.bf16.bf16.f32 "
        "{%0,%1,%2,%3},{%4,%5,%6,%7},{%8,%9},{%0,%1,%2,%3};"
        : "+f"(c[0]), "+f"(c[1]), "+f"(c[2]), "+f"(c[3])
        : "r"(a[0]), "r"(a[1]), "r"(a[2]), "r"(a[3]), "r"(b[0]), "r"(b[1]));
}
__device__ __forceinline__ float ex2(float x) {
    float r; asm("ex2.approx.f32 %0, %1;" : "=f"(r) : "f"(x)); return r;
}
__device__ __forceinline__ uint32_t pk(float a, float b) {
    __nv_bfloat162 v = __floats2bfloat162_rn(a, b);
    return *reinterpret_cast<uint32_t*>(&v);
}
__device__ __forceinline__ uint4 pk8(float4 a, float4 b) {
    uint4 o;
    o.x = pk(a.x, a.y); o.y = pk(a.z, a.w);
    o.z = pk(b.x, b.y); o.w = pk(b.z, b.w);
    return o;
}

// ------------------------- K0: one fused prep kernel -----------------------
__device__ __forceinline__ int read_count(const void* p, int i, bool is64) {
    if (is64) return (int)((const long long*)p)[i];
    return ((const int*)p)[i];
}

// grid 193 blocks x 256 thr:
//  b==0      : counts/offsets, BN->affine, biases (bkv, bqy incl. b1')
//  b 1..128  : W1bp rows 2(b-1), 2(b-1)+1  (W1b @ Wm, permuted cols)
//  b 129..192: weight conversions (Wkv, Wqy, W2)
__global__ void k_prep_all(const void* snv, const void* dnv,
                           const float* __restrict__ Wq, const float* __restrict__ bq,
                           const float* __restrict__ Wk, const float* __restrict__ bk,
                           const float* __restrict__ Wv, const float* __restrict__ bv,
                           const float* __restrict__ Wm, const float* __restrict__ bm,
                           const float* __restrict__ W1, const float* __restrict__ b1,
                           const float* __restrict__ g1, const float* __restrict__ be1,
                           const float* __restrict__ rm1, const float* __restrict__ rv1,
                           const float* __restrict__ W2,
                           const float* __restrict__ g2, const float* __restrict__ be2,
                           const float* __restrict__ rm2, const float* __restrict__ rv2)
{
    const int b = blockIdx.x, t = threadIdx.x;
    if (b == 0) {
        bool s64 = (((const int*)snv)[1] == 0);
        bool d64 = (((const int*)dnv)[1] == 0);
        __shared__ int sc[NSEG], dc[NSEG];
        __shared__ float bms[128];
        if (t < NSEG) {
            sc[t] = read_count(snv, t, s64);
            dc[t] = read_count(dnv, t, d64);
        }
        if (t < 128) bms[t] = bm[t];
        __syncthreads();
        if (t == 0) {
            int ss = 0, dd = 0;
            for (int i = 0; i < NSEG; i++) {
                g_soff[i] = ss; g_doff[i] = dd;
                g_scnt[i] = sc[i]; g_dcnt[i] = dc[i];
                ss += sc[i]; dd += dc[i];
            }
            g_soff[NSEG] = ss; g_doff[NSEG] = dd;
        }
        {
            float s1v = g1[t] * rsqrtf(rv1[t] + 1e-5f);
            g_s1[t] = s1v; g_t1[t] = be1[t] - rm1[t] * s1v;
            float s2v = g2[t] * rsqrtf(rv2[t] + 1e-5f);
            g_s2[t] = s2v; g_t2[t] = be2[t] - rm2[t] * s2v;
        }
        g_bkv[t] = (t < 128) ? bk[permc(t)] : bv[permc(t - 128)];
        if (t < 128) g_bqy[t] = bq[permc(t)];
        {   // b1' = b1 + W1b @ bm  -> g_bqy[128 + r]
            float a0 = 0.f, a1 = 0.f, a2 = 0.f, a3 = 0.f;
            const float* wrow = W1 + t * 384 + 256;
            #pragma unroll
            for (int j = 0; j < 128; j += 4) {
                a0 += wrow[j] * bms[j];     a1 += wrow[j + 1] * bms[j + 1];
                a2 += wrow[j + 2] * bms[j + 2]; a3 += wrow[j + 3] * bms[j + 3];
            }
            g_bqy[128 + t] = b1[t] + ((a0 + a1) + (a2 + a3));
        }
    } else if (b <= 128) {
        // W1bp: rows r0, r0+1 of (W1b @ Wm) with head-major column permute
        __shared__ float w1s[2][128];
        const int r0 = (b - 1) * 2;
        { int rr = t >> 7, cc = t & 127; w1s[rr][cc] = W1[(r0 + rr) * 384 + 256 + cc]; }
        __syncthreads();
        const int rr = t >> 7, cp = t & 127;      // cp: column of Wm (coalesced)
        float a0 = 0.f, a1 = 0.f, a2 = 0.f, a3 = 0.f;
        #pragma unroll
        for (int j = 0; j < 128; j += 4) {
            a0 += w1s[rr][j]     * Wm[(j)     * 128 + cp];
            a1 += w1s[rr][j + 1] * Wm[(j + 1) * 128 + cp];
            a2 += w1s[rr][j + 2] * Wm[(j + 2) * 128 + cp];
            a3 += w1s[rr][j + 3] * Wm[(j + 3) * 128 + cp];
        }
        const int co = (cp & 3) * 32 + (cp >> 2); // head-major position of cp
        g_W1bp[(r0 + rr) * 128 + co] = __float2bfloat16((a0 + a1) + (a2 + a3));
    } else {
        const int base = (b - 129) * 256 + t;     // stride 16384 over 64 blocks
        for (int i = base; i < 256 * 256; i += 64 * 256) {
            int n = i >> 8, k = i & 255;
            float v = (n < 128) ? Wk[permc(n) * 256 + k] : Wv[permc(n - 128) * 256 + k];
            g_Wkv[i] = __float2bfloat16(v);
        }
        for (int i = base; i < 384 * 256; i += 64 * 256) {
            int n = i >> 8, k = i & 255;
            float v = (n < 128) ? Wq[permc(n) * 256 + k] : W1[(n - 128) * 384 + k];
            g_Wqy[i] = __float2bfloat16(v);
        }
        for (int i = base; i < 256 * 256; i += 64 * 256) {
            g_W2b[i] = __float2bfloat16(W2[i]);
        }
    }
}

// ------------------------------ bf16 MMA GEMM ------------------------------
// C[M,N] = A[M,K](fp32, converted on load) @ W[N,K](bf16)^T + epilogue.
// 128x128 block, BK=32, 256 thr = 8 warps (2m x 4n), warp tile 64x32.
// MODE 0: C = acc + bias (OBF chooses bf16/fp32 out)
// MODE 3: col<128 -> bf16 q (ld 128) ; col>=128 -> fp32 y1a (ld 256, col-128)
template<int MODE, bool OBF>
__global__ __launch_bounds__(256) void k_gemm(
    const float* __restrict__ A, int K,
    const __nv_bfloat16* __restrict__ W,
    const float* __restrict__ bias,
    void* __restrict__ Cv, int N,
    float* __restrict__ C2)
{
    __shared__ __align__(16) __nv_bfloat16 As[128 * 32];
    __shared__ __align__(16) __nv_bfloat16 Bs[128 * 32];
    const int t = threadIdx.x, lane = t & 31, w = t >> 5;
    const int mw = w >> 2, nw = w & 3;               // 2 x 4 warps
    const int m0 = blockIdx.x * 128, n0 = blockIdx.y * 128;

    const int rA = t >> 2, kc = t & 3;
    const int swz = kc ^ ((rA >> 1) & 3);
    const float* Ag0 = A + (size_t)(m0 + rA) * K + kc * 8;
    const float* Ag1 = Ag0 + (size_t)64 * K;
    const __nv_bfloat16* Wg0 = W + (size_t)(n0 + rA) * K + kc * 8;
    const __nv_bfloat16* Wg1 = Wg0 + (size_t)64 * K;
    __nv_bfloat16* sA0 = As + (rA * 4 + swz) * 8;
    __nv_bfloat16* sA1 = As + ((rA + 64) * 4 + swz) * 8;
    __nv_bfloat16* sB0 = Bs + (rA * 4 + swz) * 8;
    __nv_bfloat16* sB1 = Bs + ((rA + 64) * 4 + swz) * 8;
    const uint32_t baseA = (uint32_t)__cvta_generic_to_shared(As);
    const uint32_t baseB = (uint32_t)__cvta_generic_to_shared(Bs);

    float acc[4][4][4] = {};
    float4 a0l = *(const float4*)Ag0, a0h = *(const float4*)(Ag0 + 4);
    float4 a1l = *(const float4*)Ag1, a1h = *(const float4*)(Ag1 + 4);
    uint4 pb0 = *(const uint4*)Wg0, pb1 = *(const uint4*)Wg1;

    for (int kt = 0; kt < K; kt += 32) {
        *(uint4*)sA0 = pk8(a0l, a0h);
        *(uint4*)sA1 = pk8(a1l, a1h);
        *(uint4*)sB0 = pb0;
        *(uint4*)sB1 = pb1;
        __syncthreads();
        if (kt + 32 < K) {
            a0l = *(const float4*)(Ag0 + kt + 32); a0h = *(const float4*)(Ag0 + kt + 36);
            a1l = *(const float4*)(Ag1 + kt + 32); a1h = *(const float4*)(Ag1 + kt + 36);
            pb0 = *(const uint4*)(Wg0 + kt + 32);  pb1 = *(const uint4*)(Wg1 + kt + 32);
        }
        #pragma unroll
        for (int kk = 0; kk < 2; kk++) {
            uint32_t af[4][4];
            #pragma unroll
            for (int f = 0; f < 4; f++) {
                int row = mw * 64 + f * 16 + (lane & 15);
                int c8 = (kk * 2 + (lane >> 4)) ^ ((row >> 1) & 3);
                ldsm4(af[f][0], af[f][1], af[f][2], af[f][3],
                      baseA + (row * 4 + c8) * 16);
            }
            uint32_t bfr[2][4];
            #pragma unroll
            for (int p = 0; p < 2; p++) {
                int row = nw * 32 + p * 16 + (lane & 7) + ((lane >> 4) << 3);
                int c8 = (kk * 2 + ((lane >> 3) & 1)) ^ ((row >> 1) & 3);
                ldsm4(bfr[p][0], bfr[p][1], bfr[p][2], bfr[p][3],
                      baseB + (row * 4 + c8) * 16);
            }
            #pragma unroll
            for (int f = 0; f < 4; f++)
                #pragma unroll
                for (int n = 0; n < 4; n++)
                    mma_bf16(acc[f][n], af[f], &bfr[n >> 1][(n & 1) * 2]);
        }
        __syncthreads();
    }

    const int er = m0 + mw * 64 + (lane >> 2);
    const int ec = n0 + nw * 32 + (lane & 3) * 2;
    #pragma unroll
    for (int f = 0; f < 4; f++)
        #pragma unroll
        for (int n = 0; n < 4; n++)
            #pragma unroll
            for (int half = 0; half < 2; half++) {
                int r = er + f * 16 + half * 8;
                int c = ec + n * 8;
                float x0 = acc[f][n][half * 2] + bias[c];
                float x1 = acc[f][n][half * 2 + 1] + bias[c + 1];
                if (MODE == 3) {
                    if (n0 == 0) {
                        *(__nv_bfloat162*)((__nv_bfloat16*)Cv + (size_t)r * 128 + c) =
                            __floats2bfloat162_rn(x0, x1);
                    } else {
                        *(float2*)(C2 + (size_t)r * 256 + (c - 128)) =
                            make_float2(x0, x1);
                    }
                } else if (OBF) {
                    *(__nv_bfloat162*)((__nv_bfloat16*)Cv + (size_t)r * N + c) =
                        __floats2bfloat162_rn(x0, x1);
                } else {
                    *(float2*)((float*)Cv + (size_t)r * N + c) = make_float2(x0, x1);
                }
            }
}

// ------------------------------- Attention ---------------------------------
// 64 dst rows / block; 8 warps = 4 heads x 2 q-halves; 64-row kv tiles.
__global__ __launch_bounds__(256) void k_attn()
{
    __shared__ __align__(16) __nv_bfloat16 qs[64 * 128];   // 16KB
    __shared__ __align__(16) __nv_bfloat16 ks[64 * 256];   // 32KB
    const int b = blockIdx.y, q0 = blockIdx.x * 64;
    const int nd = g_dcnt[b];
    if (q0 >= nd) return;
    const int ns = g_scnt[b], soff = g_soff[b], doff = g_doff[b];
    const int nQ = min(64, nd - q0);
    const int t = threadIdx.x, lane = t & 31, w = t >> 5;
    const int h = w & 3, qh = w >> 2;

    #pragma unroll
    for (int i = 0; i < 4; i++) {
        int idx = t + i * 256;
        int row = idx >> 4, c = idx & 15;
        uint4 v = make_uint4(0, 0, 0, 0);
        if (row < nQ)
            v = *(const uint4*)(g_q + (size_t)(doff + q0 + row) * 128 + c * 8);
        *(uint4*)(qs + (row * 16 + (c ^ (row & 7))) * 8) = v;
    }

    const uint32_t baseQ = (uint32_t)__cvta_generic_to_shared(qs);
    const uint32_t baseK = (uint32_t)__cvta_generic_to_shared(ks);
    float acc[2][4][4] = {};
    float den[2][2] = {};
    const float sc2 = 0.25504167f;   // log2(e)/sqrt(32)

    const int nT = (ns + 63) >> 6;
    for (int tt = 0; tt < nT; tt++) {
        __syncthreads();
        #pragma unroll
        for (int i = 0; i < 8; i++) {
            int idx = t + i * 256;
            int row = idx >> 5, c = idx & 31;
            int gr = soff + tt * 64 + row; if (gr >= TOTAL) gr = TOTAL - 1;
            uint4 v = *(const uint4*)(g_kv + (size_t)gr * 256 + c * 8);
            *(uint4*)(ks + (row * 32 + (c ^ (row & 7))) * 8) = v;
        }
        __syncthreads();

        #pragma unroll
        for (int hh = 0; hh < 2; hh++) {
            const int s0 = tt * 64 + hh * 32;
            if (s0 >= ns) break;
            const int kr0 = hh * 32;

            // ---- S = Q K^T (per head, K=32) ----
            float S[2][4][4] = {};
            #pragma unroll
            for (int kk = 0; kk < 2; kk++) {
                uint32_t af[2][4];
                #pragma unroll
                for (int f = 0; f < 2; f++) {
                    int row = qh * 32 + f * 16 + (lane & 15);
                    int c8 = (h * 4 + kk * 2 + (lane >> 4)) ^ (row & 7);
                    ldsm4(af[f][0], af[f][1], af[f][2], af[f][3],
                          baseQ + (row * 16 + c8) * 16);
                }
                uint32_t bk2[2][4];
                #pragma unroll
                for (int p = 0; p < 2; p++) {
                    int row = kr0 + p * 16 + (lane & 7) + ((lane >> 4) << 3);
                    int c8 = (h * 4 + kk * 2 + ((lane >> 3) & 1)) ^ (row & 7);
                    ldsm4(bk2[p][0], bk2[p][1], bk2[p][2], bk2[p][3],
                          baseK + (row * 32 + c8) * 16);
                }
                #pragma unroll
                for (int f = 0; f < 2; f++)
                    #pragma unroll
                    for (int n = 0; n < 4; n++)
                        mma_bf16(S[f][n], af[f], &bk2[n >> 1][(n & 1) * 2]);
            }

            // ---- exp + mask + den, pack P into A fragments ----
            uint32_t Ap[2][2][4];
            #pragma unroll
            for (int f = 0; f < 2; f++) {
                float d0 = 0.f, d1 = 0.f;
                #pragma unroll
                for (int n = 0; n < 4; n++) {
                    int cb = s0 + n * 8 + (lane & 3) * 2;
                    float e0 = ex2(S[f][n][0] * sc2); if (cb >= ns) e0 = 0.f;
                    float e1 = ex2(S[f][n][1] * sc2); if (cb + 1 >= ns) e1 = 0.f;
                    float e2 = ex2(S[f][n][2] * sc2); if (cb >= ns) e2 = 0.f;
                    float e3 = ex2(S[f][n][3] * sc2); if (cb + 1 >= ns) e3 = 0.f;
                    d0 += e0 + e1; d1 += e2 + e3;
                    Ap[f][n >> 1][(n & 1) * 2]     = pk(e0, e1);
                    Ap[f][n >> 1][(n & 1) * 2 + 1] = pk(e2, e3);
                }
                den[f][0] += d0; den[f][1] += d1;
            }

            // ---- O += P V (V B-frags via ldmatrix.trans) ----
            #pragma unroll
            for (int kk = 0; kk < 2; kk++) {
                uint32_t bv[2][4];
                #pragma unroll
                for (int p = 0; p < 2; p++) {
                    int row = kr0 + kk * 16 + (lane & 15);
                    int c8 = (16 + h * 4 + p * 2 + (lane >> 4)) ^ (row & 7);
                    ldsm4t(bv[p][0], bv[p][1], bv[p][2], bv[p][3],
                           baseK + (row * 32 + c8) * 16);
                }
                #pragma unroll
                for (int f = 0; f < 2; f++)
                    #pragma unroll
                    for (int n = 0; n < 4; n++)
                        mma_bf16(acc[f][n], Ap[f][kk], &bv[n >> 1][(n & 1) * 2]);
            }
        }
    }

    #pragma unroll
    for (int f = 0; f < 2; f++)
        #pragma unroll
        for (int u = 0; u < 2; u++) {
            float v = den[f][u];
            v += __shfl_xor_sync(0xffffffffu, v, 1);
            v += __shfl_xor_sync(0xffffffffu, v, 2);
            den[f][u] = 1.f / v;
        }

    #pragma unroll
    for (int f = 0; f < 2; f++)
        #pragma unroll
        for (int n = 0; n < 4; n++)
            #pragma unroll
            for (int half = 0; half < 2; half++) {
                int rl = qh * 32 + f * 16 + (lane >> 2) + half * 8;
                if (rl < nQ) {
                    float inv = den[f][half];
                    __nv_bfloat162 o = __floats2bfloat162_rn(
                        acc[f][n][half * 2] * inv, acc[f][n][half * 2 + 1] * inv);
                    *(__nv_bfloat162*)(g_msg + (size_t)(doff + q0 + rl) * 128 +
                                       h * 32 + n * 8 + (lane & 3) * 2) = o;
                }
            }
}

// ------------------------- fused MLP: G3 + G4 ------------------------------
// 64 rows / block.  Phase1: x1 = relu((msg@W1bp.T + y1a)*s1+t1) -> smem (bf16)
// Phase2: out = (x1@W2.T + b2)*s2+t2 + dst_h    (x1 read straight from smem)
#define MLP_SMEM (64*256 + 64*128 + 128*32)   // bf16 elements = 57344 B

__global__ __launch_bounds__(256) void k_mlp(const float* __restrict__ dst_h,
                                             float* __restrict__ out,
                                             const float* __restrict__ b2)
{
    extern __shared__ __align__(16) __nv_bfloat16 smb[];
    __nv_bfloat16* x1s  = smb;                 // 64 x 256, swizzled chunks
    __nv_bfloat16* msgS = x1s + 64 * 256;      // 64 x 128, swizzled
    __nv_bfloat16* Bs   = msgS + 64 * 128;     // 128 x 32
    const int t = threadIdx.x, lane = t & 31, w = t >> 5;
    const int mw = w >> 2, nw = w & 3;
    const int m0 = blockIdx.x * 64;

    // stage msg tile (64 x 128 bf16)
    #pragma unroll
    for (int i = 0; i < 4; i++) {
        int idx = t + i * 256;
        int row = idx >> 4, c = idx & 15;
        uint4 v = *(const uint4*)(g_msg + (size_t)(m0 + row) * 128 + c * 8);
        *(uint4*)(msgS + (row * 16 + (c ^ (row & 7))) * 8) = v;
    }

    const uint32_t baseM = (uint32_t)__cvta_generic_to_shared(msgS);
    const uint32_t baseX = (uint32_t)__cvta_generic_to_shared(x1s);
    const uint32_t baseB = (uint32_t)__cvta_generic_to_shared(Bs);
    const int rB = t >> 2, kc = t & 3;
    const int swz = kc ^ ((rB >> 1) & 3);
    __nv_bfloat16* sB0 = Bs + (rB * 4 + swz) * 8;
    __nv_bfloat16* sB1 = Bs + ((rB + 64) * 4 + swz) * 8;

    // ---------------- phase 1: x1 tile ----------------
    #pragma unroll
    for (int p = 0; p < 2; p++) {
        float acc[2][4][4] = {};
        for (int kt = 0; kt < 4; kt++) {       // K = 128
            __syncthreads();
            *(uint4*)sB0 = *(const uint4*)(g_W1bp + (size_t)(p * 128 + rB) * 128 + kt * 32 + kc * 8);
            *(uint4*)sB1 = *(const uint4*)(g_W1bp + (size_t)(p * 128 + rB + 64) * 128 + kt * 32 + kc * 8);
            __syncthreads();
            #pragma unroll
            for (int kk = 0; kk < 2; kk++) {
                int kidx = kt * 2 + kk;
                uint32_t af[2][4];
                #pragma unroll
                for (int f = 0; f < 2; f++) {
                    int row = mw * 32 + f * 16 + (lane & 15);
                    int c8 = (kidx * 2 + (lane >> 4)) ^ (row & 7);
                    ldsm4(af[f][0], af[f][1], af[f][2], af[f][3],
                          baseM + (row * 16 + c8) * 16);
                }
                uint32_t bfr[2][4];
                #pragma unroll
                for (int pb = 0; pb < 2; pb++) {
                    int row = nw * 32 + pb * 16 + (lane & 7) + ((lane >> 4) << 3);
                    int c8 = (kk * 2 + ((lane >> 3) & 1)) ^ ((row >> 1) & 3);
                    ldsm4(bfr[pb][0], bfr[pb][1], bfr[pb][2], bfr[pb][3],
                          baseB + (row * 4 + c8) * 16);
                }
                #pragma unroll
                for (int f = 0; f < 2; f++)
                    #pragma unroll
                    for (int n = 0; n < 4; n++)
                        mma_bf16(acc[f][n], af[f], &bfr[n >> 1][(n & 1) * 2]);
            }
        }
        // epilogue -> x1s (bf16, swizzled)
        const int erl = mw * 32 + (lane >> 2);
        const int ecl = p * 128 + nw * 32 + (lane & 3) * 2;
        #pragma unroll
        for (int f = 0; f < 2; f++)
            #pragma unroll
            for (int n = 0; n < 4; n++)
                #pragma unroll
                for (int half = 0; half < 2; half++) {
                    int rl = erl + f * 16 + half * 8;
                    int c = ecl + n * 8;
                    float2 ya = *(const float2*)(g_y1a + (size_t)(m0 + rl) * 256 + c);
                    float x0 = fmaxf((acc[f][n][half * 2] + ya.x) * g_s1[c] + g_t1[c], 0.f);
                    float x1 = fmaxf((acc[f][n][half * 2 + 1] + ya.y) * g_s1[c + 1] + g_t1[c + 1], 0.f);
                    int loc = (c >> 3) ^ (rl & 7);
                    *(__nv_bfloat162*)(x1s + (rl * 32 + loc) * 8 + (c & 7)) =
                        __floats2bfloat162_rn(x0, x1);
                }
    }

    // ---------------- phase 2: out tile ----------------
    #pragma unroll
    for (int p2 = 0; p2 < 2; p2++) {
        float acc[2][4][4] = {};
        for (int kt = 0; kt < 8; kt++) {       // K = 256
            __syncthreads();
            *(uint4*)sB0 = *(const uint4*)(g_W2b + (size_t)(p2 * 128 + rB) * 256 + kt * 32 + kc * 8);
            *(uint4*)sB1 = *(const uint4*)(g_W2b + (size_t)(p2 * 128 + rB + 64) * 256 + kt * 32 + kc * 8);
            __syncthreads();
            #pragma unroll
            for (int kk = 0; kk < 2; kk++) {
                int kidx = kt * 2 + kk;
                uint32_t af[2][4];
                #pragma unroll
                for (int f = 0; f < 2; f++) {
                    int row = mw * 32 + f * 16 + (lane & 15);
                    int c8 = (kidx * 2 + (lane >> 4)) ^ (row & 7);
                    ldsm4(af[f][0], af[f][1], af[f][2], af[f][3],
                          baseX + (row * 32 + c8) * 16);
                }
                uint32_t bfr[2][4];
                #pragma unroll
                for (int pb = 0; pb < 2; pb++) {
                    int row = nw * 32 + pb * 16 + (lane & 7) + ((lane >> 4) << 3);
                    int c8 = (kk * 2 + ((lane >> 3) & 1)) ^ ((row >> 1) & 3);
                    ldsm4(bfr[pb][0], bfr[pb][1], bfr[pb][2], bfr[pb][3],
                          baseB + (row * 4 + c8) * 16);
                }
                #pragma unroll
                for (int f = 0; f < 2; f++)
                    #pragma unroll
                    for (int n = 0; n < 4; n++)
                        mma_bf16(acc[f][n], af[f], &bfr[n >> 1][(n & 1) * 2]);
            }
        }
        const int erl = mw * 32 + (lane >> 2);
        const int ecl = p2 * 128 + nw * 32 + (lane & 3) * 2;
        #pragma unroll
        for (int f = 0; f < 2; f++)
            #pragma unroll
            for (int n = 0; n < 4; n++)
                #pragma unroll
                for (int half = 0; half < 2; half++) {
                    int rl = erl + f * 16 + half * 8;
                    int c = ecl + n * 8;
                    int r = m0 + rl;
                    float2 dh = *(const float2*)(dst_h + (size_t)r * 256 + c);
                    float x0 = (acc[f][n][half * 2] + b2[c]) * g_s2[c] + g_t2[c] + dh.x;
                    float x1 = (acc[f][n][half * 2 + 1] + b2[c + 1]) * g_s2[c + 1] + g_t2[c + 1] + dh.y;
                    *(float2*)(out + (size_t)r * 256 + c) = make_float2(x0, x1);
                }
    }
}

// ------------------------------- launcher ----------------------------------
extern "C" void kernel_launch(void* const* d_in, const int* in_sizes, int n_in,
                              void* d_out, int out_size)
{
    const float* src_h = (const float*)d_in[0];
    const float* dst_h = (const float*)d_in[1];
    const void*  snv   = d_in[2];
    const void*  dnv   = d_in[3];
    const float* Wq = (const float*)d_in[4];  const float* bq = (const float*)d_in[5];
    const float* Wk = (const float*)d_in[6];  const float* bk = (const float*)d_in[7];
    const float* Wv = (const float*)d_in[8];  const float* bv = (const float*)d_in[9];
    const float* Wm = (const float*)d_in[10]; const float* bm = (const float*)d_in[11];
    const float* W1 = (const float*)d_in[12]; const float* b1 = (const float*)d_in[13];
    const float* g1 = (const float*)d_in[14]; const float* be1 = (const float*)d_in[15];
    const float* rm1 = (const float*)d_in[16]; const float* rv1 = (const float*)d_in[17];
    const float* W2 = (const float*)d_in[18]; const float* b2 = (const float*)d_in[19];
    const float* g2 = (const float*)d_in[20]; const float* be2 = (const float*)d_in[21];
    const float* rm2 = (const float*)d_in[22]; const float* rv2 = (const float*)d_in[23];
    float* out = (float*)d_out;

    __nv_bfloat16 *p_kv, *p_q, *p_Wkv, *p_Wqy;
    float *p_y1a, *p_bkv, *p_bqy;
    cudaGetSymbolAddress((void**)&p_kv, g_kv);
    cudaGetSymbolAddress((void**)&p_q, g_q);
    cudaGetSymbolAddress((void**)&p_y1a, g_y1a);
    cudaGetSymbolAddress((void**)&p_Wkv, g_Wkv);
    cudaGetSymbolAddress((void**)&p_Wqy, g_Wqy);
    cudaGetSymbolAddress((void**)&p_bkv, g_bkv);
    cudaGetSymbolAddress((void**)&p_bqy, g_bqy);

    static bool attr_set = false;
    if (!attr_set) {
        cudaFuncSetAttribute(k_mlp, cudaFuncAttributeMaxDynamicSharedMemorySize,
                             MLP_SMEM * (int)sizeof(__nv_bfloat16));
        attr_set = true;
    }

    // 1. fused prep
    k_prep_all<<<193, 256>>>(snv, dnv, Wq, bq, Wk, bk, Wv, bv, Wm, bm,
                             W1, b1, g1, be1, rm1, rv1, W2, g2, be2, rm2, rv2);
    // 2. kv = src_h @ [Wk;Wv]'.T  (bf16, head-major)
    k_gemm<0, true><<<dim3(192, 2), 256>>>(src_h, 256, p_Wkv, p_bkv, p_kv, 256, nullptr);
    // 3. q | y1a = dst_h @ [Wq;W1a].T
    k_gemm<3, true><<<dim3(192, 3), 256>>>(dst_h, 256, p_Wqy, p_bqy, p_q, 128, p_y1a);
    // 4. attention
    k_attn<<<dim3(8, NSEG), 256>>>();
    // 5. fused MLP (G3+G4) + residual
    k_mlp<<<384, 256, MLP_SMEM * (int)sizeof(__nv_bfloat16)>>>(dst_h, out, b2);
}